// round 3
// baseline (speedup 1.0000x reference)
#include <cuda_runtime.h>
#include <math.h>

// Problem constants
#define PARTS   5
#define BATCH   128
#define SEQ     300
#define DP      30
#define HID     512
#define CLASSES 60
#define IN_DIM  150          // PARTS*DP
#define GATES3  1536         // 3*HID
#define NB      8192         // PARTS*GATES3 + HID   (gate cols + o_pre cols)
#define KA      662          // IN_DIM + HID
#define KP      672          // KA padded to multiple of 16

// GEMM tiling
#define BK 16
#define BN 64
#define TM 8
#define TN 4

// Scratch (device globals — no allocation allowed)
__device__ float g_W[KP * NB];              // packed weights, 21.7 MB
__device__ float g_bias[NB];
__device__ float g_A[BATCH * KP];           // [x_flat | h | pad] per batch row
__device__ float g_G[BATCH * NB];           // gate pre-activations
__device__ float g_c[BATCH * PARTS * HID];  // per-part cell state

__device__ __forceinline__ float sigf(float x) { return 1.0f / (1.0f + expf(-x)); }

// ---------------------------------------------------------------------------
// Pack W once per launch (idempotent, deterministic).
// Column layout: n in [0, 7680): part p = n/1536, gate index gi = n%1536
//                n in [7680, 8192): o_pre column j = n-7680
// Row layout:    k in [0,150): x_flat (part p occupies k in [p*30, p*30+30))
//                k in [150,662): h ; k in [662,672): zero pad
// ---------------------------------------------------------------------------
__global__ void pack_kernel(const float* __restrict__ Wx, const float* __restrict__ Wh,
                            const float* __restrict__ Wxo, const float* __restrict__ Who) {
    int idx = blockIdx.x * blockDim.x + threadIdx.x;
    const int total = KP * NB;
    for (; idx < total; idx += gridDim.x * blockDim.x) {
        int k = idx / NB;
        int n = idx % NB;
        float v = 0.0f;
        if (n < PARTS * GATES3) {
            int p  = n / GATES3;
            int gi = n % GATES3;
            if (k < IN_DIM) {
                if (k >= p * DP && k < p * DP + DP)
                    v = Wx[k * GATES3 + gi];          // (p*DP + d) == k
            } else if (k < KA) {
                v = Wh[(p * HID + (k - IN_DIM)) * GATES3 + gi];
            }
        } else {
            int j = n - PARTS * GATES3;
            if (k < IN_DIM)      v = Wxo[k * HID + j];
            else if (k < KA)     v = Who[(k - IN_DIM) * HID + j];
        }
        g_W[idx] = v;
    }
}

__global__ void bias_kernel(const float* __restrict__ bvec, const float* __restrict__ bo) {
    int n = blockIdx.x * blockDim.x + threadIdx.x;
    if (n >= NB) return;
    if (n < PARTS * GATES3) g_bias[n] = bvec[(n / GATES3) * GATES3 + (n % GATES3)];
    else                    g_bias[n] = bo[n - PARTS * GATES3];
}

// Zero c, build A for t=0 (h=0, pad=0, x_0 gathered).
__global__ void init_kernel(const float* __restrict__ x) {
    int idx = blockIdx.x * blockDim.x + threadIdx.x;
    const int nA = BATCH * KP;
    const int total = nA + BATCH * PARTS * HID;
    for (; idx < total; idx += gridDim.x * blockDim.x) {
        if (idx < nA) {
            int b = idx / KP, k = idx % KP;
            float v = 0.0f;
            if (k < IN_DIM) {
                int p = k / DP, d = k % DP;
                v = x[((p * BATCH + b) * SEQ + 0) * DP + d];
            }
            g_A[idx] = v;
        } else {
            g_c[idx - nA] = 0.0f;
        }
    }
}

// ---------------------------------------------------------------------------
// Step GEMM: G[128, 8192] = A[128, 672] @ W[672, 8192] + bias
// One block per 64-column stripe (grid = 128). 256 threads, 8x4 per thread.
// ---------------------------------------------------------------------------
__global__ void __launch_bounds__(256) gemm_kernel() {
    __shared__ float As[BK][BATCH];
    __shared__ float Bs[BK][BN];

    const int tid = threadIdx.x;
    const int n0  = blockIdx.x * BN;
    const int tr  = tid >> 4;   // 0..15  (row group, TM=8 -> covers 128)
    const int tc  = tid & 15;   // 0..15  (col group, TN=4 -> covers 64)

    float acc[TM][TN];
#pragma unroll
    for (int i = 0; i < TM; i++)
#pragma unroll
        for (int j = 0; j < TN; j++) acc[i][j] = 0.0f;

    // B-tile load indices (reused each iter)
    const int brow = tid >> 4;   // 0..15
    const int bc4  = tid & 15;   // 0..15 -> float4 column

    for (int k0 = 0; k0 < KP; k0 += BK) {
        // A tile 128x16 = 512 float4; 2 per thread, store transposed
#pragma unroll
        for (int l = 0; l < 2; l++) {
            int idx = tid + l * 256;
            int row = idx >> 2;
            int kq  = idx & 3;
            float4 v = *reinterpret_cast<const float4*>(&g_A[row * KP + k0 + kq * 4]);
            As[kq * 4 + 0][row] = v.x;
            As[kq * 4 + 1][row] = v.y;
            As[kq * 4 + 2][row] = v.z;
            As[kq * 4 + 3][row] = v.w;
        }
        // B tile 16x64 = 256 float4; 1 per thread
        {
            float4 v = *reinterpret_cast<const float4*>(&g_W[(k0 + brow) * NB + n0 + bc4 * 4]);
            *reinterpret_cast<float4*>(&Bs[brow][bc4 * 4]) = v;
        }
        __syncthreads();

#pragma unroll
        for (int kk = 0; kk < BK; kk++) {
            float a[TM], bb[TN];
#pragma unroll
            for (int i = 0; i < TM; i++) a[i] = As[kk][tr * TM + i];
#pragma unroll
            for (int j = 0; j < TN; j++) bb[j] = Bs[kk][tc * TN + j];
#pragma unroll
            for (int i = 0; i < TM; i++)
#pragma unroll
                for (int j = 0; j < TN; j++) acc[i][j] += a[i] * bb[j];
        }
        __syncthreads();
    }

#pragma unroll
    for (int i = 0; i < TM; i++) {
        int row = tr * TM + i;
#pragma unroll
        for (int j = 0; j < TN; j++) {
            int col = n0 + tc * TN + j;
            g_G[row * NB + col] = acc[i][j] + g_bias[col];
        }
    }
}

// ---------------------------------------------------------------------------
// Cell update: c_new = sig(f)*c + sig(i)*tanh(g); h = sig(o)*tanh(sum_p c_new)
// Writes h into A, gathers x_{t+1} into A. grid=(BATCH), block=(HID).
// ---------------------------------------------------------------------------
__global__ void cell_kernel(const float* __restrict__ x, int t) {
    const int b  = blockIdx.x;
    const int hh = threadIdx.x;
    const float* Gr = g_G + b * NB;

    float csum = 0.0f;
#pragma unroll
    for (int p = 0; p < PARTS; p++) {
        float iv = Gr[p * GATES3 + hh];
        float fv = Gr[p * GATES3 + HID + hh];
        float gv = Gr[p * GATES3 + 2 * HID + hh];
        float co = g_c[(b * PARTS + p) * HID + hh];
        float cn = sigf(fv) * co + sigf(iv) * tanhf(gv);
        g_c[(b * PARTS + p) * HID + hh] = cn;
        csum += cn;
    }
    float o = sigf(Gr[PARTS * GATES3 + hh]);
    g_A[b * KP + IN_DIM + hh] = o * tanhf(csum);

    if (hh < IN_DIM && t + 1 < SEQ) {
        int p = hh / DP, d = hh % DP;
        g_A[b * KP + hh] = x[((p * BATCH + b) * SEQ + (t + 1)) * DP + d];
    }
}

// ---------------------------------------------------------------------------
// Classifier + log_softmax. grid=(BATCH), block=(64).
// ---------------------------------------------------------------------------
__global__ void head_kernel(const float* __restrict__ fc_w, const float* __restrict__ fc_b,
                            float* __restrict__ out) {
    __shared__ float logits[CLASSES];
    const int b = blockIdx.x;
    const int c = threadIdx.x;
    if (c < CLASSES) {
        float acc = fc_b[c];
        const float* h = g_A + b * KP + IN_DIM;
        for (int k = 0; k < HID; k++) acc += h[k] * fc_w[k * CLASSES + c];
        logits[c] = acc;
    }
    __syncthreads();
    if (c < CLASSES) {
        float m = -1e30f;
        for (int j = 0; j < CLASSES; j++) m = fmaxf(m, logits[j]);
        float s = 0.0f;
        for (int j = 0; j < CLASSES; j++) s += expf(logits[j] - m);
        out[b * CLASSES + c] = logits[c] - m - logf(s);
    }
}

extern "C" void kernel_launch(void* const* d_in, const int* in_sizes, int n_in,
                              void* d_out, int out_size) {
    const float* inputs = (const float*)d_in[0];
    const float* Wx     = (const float*)d_in[1];
    const float* Wh     = (const float*)d_in[2];
    const float* bvec   = (const float*)d_in[3];
    const float* Wxo    = (const float*)d_in[4];
    const float* Who    = (const float*)d_in[5];
    const float* bo     = (const float*)d_in[6];
    const float* fc_w   = (const float*)d_in[7];
    const float* fc_b   = (const float*)d_in[8];
    float* out = (float*)d_out;

    pack_kernel<<<2048, 256>>>(Wx, Wh, Wxo, Who);
    bias_kernel<<<(NB + 255) / 256, 256>>>(bvec, bo);
    init_kernel<<<512, 256>>>(inputs);

    for (int t = 0; t < SEQ; t++) {
        gemm_kernel<<<NB / BN, 256>>>();
        cell_kernel<<<BATCH, HID>>>(inputs, t);
    }

    head_kernel<<<BATCH, 64>>>(fc_w, fc_b, out);
}